// round 16
// baseline (speedup 1.0000x reference)
#include <cuda_runtime.h>

#define TT 4096
#define BB 32
#define DD 128
#define D3 384
#define NSTAGE 16

__device__ float g_xi[(size_t)TT * BB * D3];
__device__ int g_reset_mode;  // 0 = int32, 1 = float32, 2 = uint8/bool
__device__ int g_ready[TT];   // per-timestep xi completion flags

__device__ __forceinline__ int read_reset(const void* r, int idx, int mode) {
    if (mode == 0) return ((const int*)r)[idx] != 0;
    if (mode == 1) return ((const float*)r)[idx] != 0.0f;
    return ((const unsigned char*)r)[idx] != 0;
}

__device__ __forceinline__ unsigned long long pack2(float lo, float hi) {
    unsigned long long p;
    asm("mov.b64 %0, {%1, %2};" : "=l"(p) : "f"(lo), "f"(hi));
    return p;
}

__device__ __forceinline__ void fma2(unsigned long long& acc,
                                     unsigned long long a,
                                     unsigned long long b) {
    asm("fma.rn.f32x2 %0, %1, %2, %0;" : "+l"(acc) : "l"(a), "l"(b));
}

__device__ __forceinline__ unsigned long long add2(unsigned long long a,
                                                   unsigned long long b) {
    unsigned long long r;
    asm("add.rn.f32x2 %0, %1, %2;" : "=l"(r) : "l"(a), "l"(b));
    return r;
}

__device__ __forceinline__ float hsum2(unsigned long long a) {
    float lo, hi;
    asm("mov.b64 {%0, %1}, %2;" : "=f"(lo), "=f"(hi) : "l"(a));
    return lo + hi;
}

__device__ __forceinline__ float tanh_fast(float x) {
    float y;
    asm("tanh.approx.f32 %0, %1;" : "=f"(y) : "f"(x));
    return y;
}

__device__ __forceinline__ void cp_async16(void* smem_dst, const void* gmem_src) {
    unsigned s = (unsigned)__cvta_generic_to_shared(smem_dst);
    asm volatile("cp.async.cg.shared.global [%0], [%1], 16;"
                 :: "r"(s), "l"(gmem_src) : "memory");
}

__device__ __forceinline__ int ld_acq(const int* p) {
    int v;
    asm volatile("ld.acquire.gpu.b32 %0, [%1];" : "=r"(v) : "l"(p) : "memory");
    return v;
}

__device__ __forceinline__ void st_rel(int* p, int v) {
    asm volatile("st.release.gpu.b32 [%0], %1;" :: "l"(p), "r"(v) : "memory");
}

// ---------------------------------------------------------------------------
// Probe resets dtype (reads 128 KB — in-bounds for every candidate layout)
// and clear the per-timestep ready flags for this replay.
// ---------------------------------------------------------------------------
__global__ void probe_clear_kernel(const unsigned int* __restrict__ r) {
    for (int i = threadIdx.x; i < TT; i += blockDim.x) g_ready[i] = 0;
    __shared__ int s_not01, s_notf;
    if (threadIdx.x == 0) { s_not01 = 0; s_notf = 0; }
    __syncthreads();
    int not01 = 0, notf = 0;
    for (int i = threadIdx.x; i < 32768; i += blockDim.x) {
        unsigned v = r[i];
        if (v != 0u && v != 1u) not01 = 1;
        if (v != 0u && v != 0x3F800000u) notf = 1;
    }
    if (not01) atomicOr(&s_not01, 1);
    if (notf)  atomicOr(&s_notf, 1);
    __syncthreads();
    if (threadIdx.x == 0)
        g_reset_mode = (!s_not01) ? 0 : ((!s_notf) ? 1 : 2);
}

// ---------------------------------------------------------------------------
// GEMM role: blocks BB..grid-1. Block gb owns timesteps t = gb + k*ngemm.
// ---------------------------------------------------------------------------
__device__ __forceinline__ void gemm_role(const float* __restrict__ x,
                                          const float* __restrict__ Wi,
                                          const float* __restrict__ bi,
                                          int gb, int ngemm) {
    __shared__ __align__(16) float xs[2][DD];
    const int j = threadIdx.x;

    unsigned long long w2[64];
#pragma unroll
    for (int k = 0; k < 64; k++)
        w2[k] = pack2(Wi[(2 * k) * D3 + j], Wi[(2 * k + 1) * D3 + j]);
    const float bj = bi[j];

    for (int t = gb; t < TT; t += ngemm) {
        const int r0 = t * BB;
        for (int rp = 0; rp < BB; rp += 2) {
            const int r = r0 + rp;
            if (j < 256)
                xs[j >> 7][j & 127] = x[(size_t)(r + (j >> 7)) * DD + (j & 127)];
            __syncthreads();

            unsigned long long a00 = 0ull, a01 = 0ull, a10 = 0ull, a11 = 0ull;
            const ulonglong2* x0 = (const ulonglong2*)xs[0];
            const ulonglong2* x1 = (const ulonglong2*)xs[1];
#pragma unroll
            for (int k = 0; k < 32; k++) {
                ulonglong2 v0 = x0[k];
                ulonglong2 v1 = x1[k];
                fma2(a00, w2[2 * k],     v0.x);
                fma2(a01, w2[2 * k + 1], v0.y);
                fma2(a10, w2[2 * k],     v1.x);
                fma2(a11, w2[2 * k + 1], v1.y);
            }
            g_xi[(size_t)r * D3 + j]       = bj + hsum2(add2(a00, a01));
            g_xi[(size_t)(r + 1) * D3 + j] = bj + hsum2(add2(a10, a11));
            __syncthreads();
        }
        __threadfence();
        __syncthreads();
        if (j == 0) st_rel(&g_ready[t], 1);
    }
}

// ---------------------------------------------------------------------------
// Scan role: blocks 0..31, one per batch element. All 384 threads dot one Wh
// column (col j == thread id; w2[64] = 128 regs, same as proven R13 loop).
//   pre-B1:  r-threads (0..127):   tot = xr + hr -> rg = sigmoid, STS srg[d]
//            z-threads (128..255): tot = xz + hz -> zg = sigmoid, STS szg[d]
//            n-threads (256..383): sn = bhn + hn stays in a REGISTER
//   B1 (__syncthreads)
//   window:  n-threads: LDS rg,zg -> ar=fmaf(rg,sn,xn) -> tanh -> nh;
//                       hprev in register; write h[p^1][d]
//            warp 0 (r-group): ys row t-1 via STG.128 from stable h[p]
//            threads 128..223 (z-group): cp.async refill of slot st
//                       (fetch timestep t+NSTAGE, wait_group(NSTAGE-1))
//   B2 (__syncthreads)
// Math identical to R13 (same MUFU op sequence) => same rel_err (~5e-6).
// ---------------------------------------------------------------------------
__device__ __forceinline__ void scan_role(const void* __restrict__ resets,
                                          const float* __restrict__ Wh,
                                          const float* __restrict__ bhn,
                                          float* __restrict__ ys, int b) {
    __shared__ __align__(16) float h[2][DD];
    __shared__ float srg[DD];
    __shared__ float szg[DD];
    __shared__ __align__(16) float xstage[NSTAGE][D3];
    __shared__ unsigned char srst[TT];

    const int j = threadIdx.x;
    const int d = j & 127;
    const int grp = j >> 7;            // 0 = r, 1 = z, 2 = n
    const int mode = g_reset_mode;

    const bool is_ys   = (j < 32);              // warp 0 (r-group)
    const bool is_refl = (j >= 128 && j < 224); // 96 z-group threads
    const int  rl = j - 128;                    // refill lane 0..95
    const int  yl = j;                          // ys lane 0..31

    // Column j of Wh, 64 f32x2 pairs (identical layout to R13's proven loop).
    unsigned long long w2[64];
#pragma unroll
    for (int k = 0; k < 64; k++)
        w2[k] = pack2(Wh[(2 * k) * D3 + j], Wh[(2 * k + 1) * D3 + j]);
    const float bn = (grp == 2) ? bhn[d] : 0.0f;

    if (j < DD) h[0][j] = 0.0f;

    for (int t = j; t < TT; t += 384)
        srst[t] = (unsigned char)read_reset(resets, t * BB + b, mode);

    // Prime the xi ring (refill threads own all cp.async group state).
    if (is_refl) {
        for (int s = 0; s < NSTAGE; s++) {
            while (ld_acq(&g_ready[s]) == 0) __nanosleep(64);
            cp_async16(&xstage[s][rl * 4],
                       g_xi + ((size_t)s * BB + b) * D3 + rl * 4);
            asm volatile("cp.async.commit_group;" ::: "memory");
        }
        // Slot 0 complete before the t=0 pre-dot xi reads.
        asm volatile("cp.async.wait_group %0;" :: "n"(NSTAGE - 1) : "memory");
    }
    __syncthreads();

    float* yp = is_ys ? (ys + (size_t)b * DD + yl * 4) : ys;

    int F = NSTAGE;       // producer frontier (refill threads, uniform)
    float hprev = 0.0f;   // n-threads: this element's current h value
    int p = 0;
    for (int t = 0; t < TT; t++) {
        const int st = t & (NSTAGE - 1);
        const int rst = srst[t];

        // Pre-dot: this thread's xi element (slot st is complete; it is only
        // overwritten by the refill AFTER B1 of this step).
        const float xi_j = xstage[st][j];

        // Dot: <Wh[:,j], h[p]> with the group's additive seed folded in.
        // seed: r -> xr (xi_j), z -> xz (xi_j), n -> bhn.
        const float seed = (grp == 2) ? bn : xi_j;
        unsigned long long a0 = pack2(seed, 0.0f), a1 = 0ull;
        const unsigned long long* hq = (const unsigned long long*)h[p];
#pragma unroll
        for (int k = 0; k < 16; k++) {
            fma2(a0, w2[4 * k + 0], hq[4 * k + 0]);
            fma2(a1, w2[4 * k + 1], hq[4 * k + 1]);
            fma2(a0, w2[4 * k + 2], hq[4 * k + 2]);
            fma2(a1, w2[4 * k + 3], hq[4 * k + 3]);
        }
        float tot = hsum2(add2(a0, a1));     // seed + <col, h>
        if (rst) tot = seed;                 // h == 0 on reset

        float sn = 0.0f;
        if (grp == 0) {
            srg[d] = 0.5f + 0.5f * tanh_fast(0.5f * tot);   // rg
        } else if (grp == 1) {
            szg[d] = 0.5f + 0.5f * tanh_fast(0.5f * tot);   // zg
        } else {
            sn = tot;                                       // bhn + hn (reg)
        }
        __syncthreads();  // B1: srg/szg published; slot-st reads done.

        // ---------- window ----------
        if (grp == 2) {
            float rg = srg[d];
            float zg = szg[d];
            float ar = fmaf(rg, sn, xi_j);   // xn + r*(hn+bhn)
            float ng = tanh_fast(ar);
            float hp = rst ? 0.0f : hprev;
            float nh = fmaf(zg, hp - ng, ng);
            hprev = nh;
            h[p ^ 1][d] = nh;
        } else if (is_ys) {
            if (t > 0) {                     // h[p] == output of step t-1
                float4 v = *(const float4*)&h[p][yl * 4];
                *(float4*)yp = v;
                yp += BB * DD;
            }
        } else if (is_refl) {
            const int need = t + NSTAGE;
            if (need < TT) {
                if (need >= F) {
                    int probe_t = need + 256;
                    if (probe_t > TT - 1) probe_t = TT - 1;
                    if (ld_acq(&g_ready[probe_t])) {
                        F = probe_t + 1;
                    } else {
                        while (ld_acq(&g_ready[need]) == 0) __nanosleep(64);
                        F = need + 1;
                    }
                }
                cp_async16(&xstage[st][rl * 4],
                           g_xi + ((size_t)need * BB + b) * D3 + rl * 4);
            }
            asm volatile("cp.async.commit_group;" ::: "memory");
            // Next step's slot (oldest pending group) complete before B2.
            asm volatile("cp.async.wait_group %0;" :: "n"(NSTAGE - 1) : "memory");
        }
        __syncthreads();  // B2: h[p^1] + refreshed slot published.
        p ^= 1;
    }

    if (is_ys) {                             // row TT-1
        float4 v = *(const float4*)&h[p][yl * 4];
        *(float4*)yp = v;
    }
}

// ---------------------------------------------------------------------------
// Fused kernel: blocks 0..31 scan, blocks 32.. run the producer GEMM.
// >=128 regs/thread -> 1 CTA/SM; grid == #SMs => all CTAs resident in wave 1,
// so the producer/consumer handshake cannot deadlock.
// ---------------------------------------------------------------------------
__global__ __launch_bounds__(384, 1)
void fused_kernel(const float* __restrict__ x,
                  const void* __restrict__ resets,
                  const float* __restrict__ Wi,
                  const float* __restrict__ bi,
                  const float* __restrict__ Wh,
                  const float* __restrict__ bhn,
                  float* __restrict__ ys,
                  int ngemm) {
    if (blockIdx.x < BB)
        scan_role(resets, Wh, bhn, ys, blockIdx.x);
    else
        gemm_role(x, Wi, bi, blockIdx.x - BB, ngemm);
}

extern "C" void kernel_launch(void* const* d_in, const int* in_sizes, int n_in,
                              void* d_out, int out_size) {
    const float* x      = (const float*)d_in[0];
    const void*  resets = d_in[1];
    const float* Wi     = (const float*)d_in[2];
    const float* bi     = (const float*)d_in[3];
    const float* Wh     = (const float*)d_in[4];
    const float* bhn    = (const float*)d_in[5];
    float* ys = (float*)d_out;

    int dev = 0, nsm = 148;
    cudaGetDevice(&dev);
    cudaDeviceGetAttribute(&nsm, cudaDevAttrMultiProcessorCount, dev);
    if (nsm < BB + 1) nsm = BB + 1;

    probe_clear_kernel<<<1, 256>>>((const unsigned int*)resets);
    fused_kernel<<<nsm, 384>>>(x, resets, Wi, bi, Wh, bhn, ys, nsm - BB);
}